// round 5
// baseline (speedup 1.0000x reference)
#include <cuda_runtime.h>
#include <cstdint>

#define F 128
#define M 2
#define ROW 1024                 // STRIDE*F*M floats per output row
#define SEGS_PER_BIN 8           // 8 rows * 4KB = 32KB smem accumulator
#define NBINS 8192               // covers 65536 segments
#define BIN_CAP 2048             // avg fill ~512; 4x headroom
#define SPILL_CAP (1u << 20)

// Static scratch (zero-init device globals; no runtime allocation)
__device__ uint2    g_bins[(size_t)NBINS * BIN_CAP];   // 134MB
__device__ unsigned g_bin_cnt[NBINS];
__device__ uint2    g_spill[SPILL_CAP];
__device__ unsigned g_spill_cnt;

// ---------------------------------------------------------------------------
__global__ void init_counters_kernel() {
    unsigned i = blockIdx.x * blockDim.x + threadIdx.x;
    if (i < NBINS) g_bin_cnt[i] = 0;
    if (i == 0) g_spill_cnt = 0;
}

// ---------------------------------------------------------------------------
// Phase 1: stream inputs once, append (local_offset, dt) to the event's bin.
// local_offset = (seg % 8)*1024 + id*2  (< 8192); channel is recoverable as
// (local_offset >> 1) & 127.
// ---------------------------------------------------------------------------
__device__ __forceinline__ void push_event(int seg, int id, float dtv) {
    unsigned bin = (unsigned)seg / SEGS_PER_BIN;
    unsigned loc = ((unsigned)seg % SEGS_PER_BIN) * ROW + (unsigned)id * M;
    if (bin < NBINS) {
        unsigned pos = atomicAdd(&g_bin_cnt[bin], 1u);
        if (pos < BIN_CAP) {
            __stcs(&g_bins[(size_t)bin * BIN_CAP + pos],
                   make_uint2(loc, __float_as_uint(dtv)));
            return;
        }
    }
    // overflow / out-of-range: spill with global offset
    unsigned s = atomicAdd(&g_spill_cnt, 1u);
    if (s < SPILL_CAP)
        g_spill[s] = make_uint2((unsigned)seg * ROW + (unsigned)id * M,
                                __float_as_uint(dtv));
}

__global__ void __launch_bounds__(256) bin_kernel(
    const float4* __restrict__ dt4,
    const int4*   __restrict__ id4,
    const int4*   __restrict__ seg4,
    int n4,
    const float* __restrict__ dt_s,
    const int*   __restrict__ id_s,
    const int*   __restrict__ seg_s,
    int n_events)
{
    int i = blockIdx.x * blockDim.x + threadIdx.x;
    if (i < n4) {
        float4 d  = __ldcs(&dt4[i]);
        int4   id = __ldcs(&id4[i]);
        int4   sg = __ldcs(&seg4[i]);
        push_event(sg.x, id.x, d.x);
        push_event(sg.y, id.y, d.y);
        push_event(sg.z, id.z, d.z);
        push_event(sg.w, id.w, d.w);
    }
    int rem = n_events & 3;
    if (blockIdx.x == 0 && threadIdx.x < rem) {
        int e = n4 * 4 + threadIdx.x;
        push_event(seg_s[e], id_s[e], dt_s[e]);
    }
}

// ---------------------------------------------------------------------------
// Phase 2: one block per bin. Accumulate the bin's events into a shared 32KB
// tile (zeroed in smem, spread shared atomics), then stream the tile to the
// output with evict-first float4 stores. No output zero pass, no global
// atomics, purely sequential output writes.
// ---------------------------------------------------------------------------
__global__ void __launch_bounds__(256) gather_kernel(
    const float* __restrict__ decay,   // [F*M]
    float* __restrict__ out,
    long long n_out)
{
    __shared__ float  acc[SEGS_PER_BIN * ROW];   // 32KB
    __shared__ float2 rate2[F];

    int t = threadIdx.x;
    // zero accumulator (32KB = 2048 float4)
    float4* acc4 = (float4*)acc;
    #pragma unroll
    for (int j = 0; j < (SEGS_PER_BIN * ROW / 4) / 256; j++)
        acc4[j * 256 + t] = make_float4(0.f, 0.f, 0.f, 0.f);
    // softplus(decay) table
    if (t < F) {
        float x0 = decay[t * M + 0];
        float x1 = decay[t * M + 1];
        rate2[t].x = fmaxf(x0, 0.f) + log1pf(expf(-fabsf(x0)));
        rate2[t].y = fmaxf(x1, 0.f) + log1pf(expf(-fabsf(x1)));
    }
    __syncthreads();

    unsigned bin = blockIdx.x;
    unsigned cnt = g_bin_cnt[bin];
    if (cnt > BIN_CAP) cnt = BIN_CAP;
    const uint2* buf = g_bins + (size_t)bin * BIN_CAP;

    // 2 events per thread per iteration (uint4 load) for MLP
    unsigned e = t * 2u;
    unsigned stride = 256u * 2u;
    for (; e + 1 < cnt; e += stride) {
        uint4 q = __ldcs((const uint4*)&buf[e]);
        {
            unsigned off = q.x; float dtv = __uint_as_float(q.y);
            float2 r = rate2[(off >> 1) & (F - 1)];
            atomicAdd(&acc[off],     __expf(-r.x * dtv));
            atomicAdd(&acc[off + 1], __expf(-r.y * dtv));
        }
        {
            unsigned off = q.z; float dtv = __uint_as_float(q.w);
            float2 r = rate2[(off >> 1) & (F - 1)];
            atomicAdd(&acc[off],     __expf(-r.x * dtv));
            atomicAdd(&acc[off + 1], __expf(-r.y * dtv));
        }
    }
    if (e < cnt) {
        uint2 q = __ldcs(&buf[e]);
        unsigned off = q.x; float dtv = __uint_as_float(q.y);
        float2 r = rate2[(off >> 1) & (F - 1)];
        atomicAdd(&acc[off],     __expf(-r.x * dtv));
        atomicAdd(&acc[off + 1], __expf(-r.y * dtv));
    }
    __syncthreads();

    // stream the tile out (handles partial last bin)
    long long seg_lo = (long long)bin * SEGS_PER_BIN;
    if (seg_lo >= n_out) return;
    long long nsegs = n_out - seg_lo;
    if (nsegs > SEGS_PER_BIN) nsegs = SEGS_PER_BIN;
    int nf4 = (int)(nsegs * ROW / 4);
    float4* dst = (float4*)(out + seg_lo * ROW);
    for (int j = t; j < nf4; j += 256)
        __stcs(&dst[j], acc4[j]);
}

// ---------------------------------------------------------------------------
// Spill fixup: global vectorized reductions for overflow events (normally 0).
// Runs after gather so its adds land on final data.
// ---------------------------------------------------------------------------
__global__ void __launch_bounds__(256) spill_kernel(
    const float* __restrict__ decay,
    float* __restrict__ out)
{
    unsigned n = g_spill_cnt;
    if (n == 0) return;
    if (n > SPILL_CAP) n = SPILL_CAP;
    __shared__ float2 rate2[F];
    int t = threadIdx.x;
    if (t < F) {
        float x0 = decay[t * M + 0];
        float x1 = decay[t * M + 1];
        rate2[t].x = fmaxf(x0, 0.f) + log1pf(expf(-fabsf(x0)));
        rate2[t].y = fmaxf(x1, 0.f) + log1pf(expf(-fabsf(x1)));
    }
    __syncthreads();
    for (unsigned e = blockIdx.x * blockDim.x + t; e < n;
         e += gridDim.x * blockDim.x) {
        uint2 q = g_spill[e];
        unsigned off = q.x; float dtv = __uint_as_float(q.y);
        float2 r = rate2[(off >> 1) & (F - 1)];
        float v0 = __expf(-r.x * dtv);
        float v1 = __expf(-r.y * dtv);
        asm volatile("red.global.add.v2.f32 [%0], {%1, %2};"
                     :: "l"(out + off), "f"(v0), "f"(v1) : "memory");
    }
}

// ---------------------------------------------------------------------------
// metadata order: 0=dt[E] f32, 1=times_out (unused), 2=decay_rate[256] f32,
//                 3=successor_kernel_channel_ids[E] i32, 4=segment_ids_out[E] i32
// output: f32[n_out*1024]
// ---------------------------------------------------------------------------
extern "C" void kernel_launch(void* const* d_in, const int* in_sizes, int n_in,
                              void* d_out, int out_size) {
    const float* dt    = (const float*)d_in[0];
    const float* decay = (const float*)d_in[2];
    const int*   ids   = (const int*)d_in[3];
    const int*   segs  = (const int*)d_in[4];
    float*       out   = (float*)d_out;

    int E  = in_sizes[0];
    int n4 = E >> 2;
    long long n_out = (long long)out_size / ROW;

    init_counters_kernel<<<(NBINS + 255) / 256, 256>>>();

    int bblocks = (n4 + 255) / 256;
    if (bblocks < 1) bblocks = 1;
    bin_kernel<<<bblocks, 256>>>(
        (const float4*)dt, (const int4*)ids, (const int4*)segs,
        n4, dt, ids, segs, E);

    long long nbins_rt = (n_out + SEGS_PER_BIN - 1) / SEGS_PER_BIN;
    if (nbins_rt > NBINS) nbins_rt = NBINS;
    gather_kernel<<<(unsigned)nbins_rt, 256>>>(decay, out, n_out);

    spill_kernel<<<64, 256>>>(decay, out);
}

// round 6
// speedup vs baseline: 1.1993x; 1.1993x over previous
#include <cuda_runtime.h>
#include <cstdint>

#define F 128
#define M 2
#define ROW 1024              // STRIDE*F*M floats per output row
#define NWIN 8                // 32MB windows: w + w+1 + draining w-1 fits L2
#define CAP (1u << 20)        // per-window bucket capacity (1M; E/8=524K expected)
#define SCAT_BLOCKS 592       // 4 blocks/SM * 148 SMs -> single wave

// Scratch: 8 windows x 1M events x 8B = 67MB (static device array, allowed)
__device__ uint2    g_buf[(size_t)NWIN * CAP];
__device__ unsigned g_cnt[NWIN];

// ---------------------------------------------------------------------------
__global__ void init_counters_kernel() {
    if (threadIdx.x < NWIN) g_cnt[threadIdx.x] = 0;
}

// ---------------------------------------------------------------------------
// Zero one window; stores allocate dirty in L2 and stay resident for the
// matching scatter pass (and force eviction of older windows' dirty lines).
// ---------------------------------------------------------------------------
__global__ void __launch_bounds__(256) zero_win_kernel(float4* __restrict__ out4,
                                                       long long n4) {
    long long i = (long long)blockIdx.x * blockDim.x + threadIdx.x;
    if (i < n4) out4[i] = make_float4(0.f, 0.f, 0.f, 0.f);
}

// ---------------------------------------------------------------------------
// Bucketize: single streaming pass. Event -> (offset = seg*1024 + id*2, dt)
// appended to its window's bucket. Block-local shared counting, one global
// atomicAdd per window per block. Bucket stores are evict-first (.cs).
// ---------------------------------------------------------------------------
__global__ void __launch_bounds__(256) bucket_kernel(
    const float4* __restrict__ dt4,
    const int4*   __restrict__ id4,
    const int4*   __restrict__ seg4,
    int n4,
    const float* __restrict__ dt_s,
    const int*   __restrict__ id_s,
    const int*   __restrict__ seg_s,
    int n_events,
    int segs_per_win)
{
    __shared__ unsigned s_cnt[NWIN];
    __shared__ unsigned s_base[NWIN];
    int t = threadIdx.x;
    if (t < NWIN) s_cnt[t] = 0;
    __syncthreads();

    int i = blockIdx.x * blockDim.x + t;

    int      w[5];
    unsigned pos[5];
    uint2    pay[5];
    int      nev = 0;

    if (i < n4) {
        float4 d  = __ldcs(&dt4[i]);
        int4   id = __ldcs(&id4[i]);
        int4   sg = __ldcs(&seg4[i]);
        float dts[4] = {d.x, d.y, d.z, d.w};
        int   ids[4] = {id.x, id.y, id.z, id.w};
        int   sgs[4] = {sg.x, sg.y, sg.z, sg.w};
        #pragma unroll
        for (int k = 0; k < 4; k++) {
            unsigned off = (unsigned)sgs[k] * ROW + (unsigned)ids[k] * M;
            int ww = sgs[k] / segs_per_win;
            w[nev]   = ww;
            pay[nev] = make_uint2(off, __float_as_uint(dts[k]));
            pos[nev] = atomicAdd(&s_cnt[ww], 1u);
            nev++;
        }
    }
    int rem = n_events & 3;
    if (blockIdx.x == 0 && t < rem) {
        int e = n4 * 4 + t;
        unsigned off = (unsigned)seg_s[e] * ROW + (unsigned)id_s[e] * M;
        int ww = seg_s[e] / segs_per_win;
        w[nev]   = ww;
        pay[nev] = make_uint2(off, __float_as_uint(dt_s[e]));
        pos[nev] = atomicAdd(&s_cnt[ww], 1u);
        nev++;
    }
    __syncthreads();

    if (t < NWIN) s_base[t] = atomicAdd(&g_cnt[t], s_cnt[t]);
    __syncthreads();

    for (int k = 0; k < nev; k++) {
        unsigned idx = s_base[w[k]] + pos[k];
        if (idx < CAP)
            __stcs(&g_buf[(size_t)w[k] * CAP + idx], pay[k]);
    }
}

// ---------------------------------------------------------------------------
// Scatter one window's bucket. Single-wave grid-stride, 4 events (2x uint4)
// per thread per iteration. Targets are L2-resident (zeroed one kernel ago)
// so red.global.add.v2.f32 is an L2-hit RMW.
// ---------------------------------------------------------------------------
__device__ __forceinline__ void fire_event(unsigned off, unsigned dt_bits,
                                           const float2* rate2,
                                           float* __restrict__ out) {
    float  dtv = __uint_as_float(dt_bits);
    float2 r   = rate2[(off >> 1) & (F - 1)];
    float v0 = __expf(-r.x * dtv);
    float v1 = __expf(-r.y * dtv);
    asm volatile("red.global.add.v2.f32 [%0], {%1, %2};"
                 :: "l"(out + off), "f"(v0), "f"(v1) : "memory");
}

__global__ void __launch_bounds__(256) scatter_bucket_kernel(
    const float* __restrict__ decay,   // [F*M]
    float* __restrict__ out,
    int w)
{
    __shared__ float2 rate2[F];
    int t = threadIdx.x;
    if (t < F) {
        float x0 = decay[t * M + 0];
        float x1 = decay[t * M + 1];
        rate2[t].x = fmaxf(x0, 0.f) + log1pf(expf(-fabsf(x0)));
        rate2[t].y = fmaxf(x1, 0.f) + log1pf(expf(-fabsf(x1)));
    }
    __syncthreads();

    unsigned cnt = g_cnt[w];
    if (cnt > CAP) cnt = CAP;
    const uint2* buf = g_buf + (size_t)w * CAP;

    unsigned stride = (unsigned)gridDim.x * blockDim.x * 4u;
    unsigned e      = ((unsigned)blockIdx.x * blockDim.x + t) * 4u;

    for (; e + 3 < cnt; e += stride) {
        uint4 qa = __ldcs((const uint4*)&buf[e]);
        uint4 qb = __ldcs((const uint4*)&buf[e + 2]);
        fire_event(qa.x, qa.y, rate2, out);
        fire_event(qa.z, qa.w, rate2, out);
        fire_event(qb.x, qb.y, rate2, out);
        fire_event(qb.z, qb.w, rate2, out);
    }
    for (; e < cnt; e++) {
        uint2 q = __ldcs(&buf[e]);
        fire_event(q.x, q.y, rate2, out);
    }
}

// ---------------------------------------------------------------------------
// metadata order: 0=dt[E] f32, 1=times_out (unused), 2=decay_rate[256] f32,
//                 3=successor_kernel_channel_ids[E] i32, 4=segment_ids_out[E] i32
// output: f32[n_out*1024]
// ---------------------------------------------------------------------------
extern "C" void kernel_launch(void* const* d_in, const int* in_sizes, int n_in,
                              void* d_out, int out_size) {
    const float* dt    = (const float*)d_in[0];
    const float* decay = (const float*)d_in[2];
    const int*   ids   = (const int*)d_in[3];
    const int*   segs  = (const int*)d_in[4];
    float*       out   = (float*)d_out;

    int E  = in_sizes[0];
    int n4 = E >> 2;

    long long n_out = (long long)out_size / ROW;
    int segs_per_win = (int)((n_out + NWIN - 1) / NWIN);

    init_counters_kernel<<<1, 32>>>();

    int bblocks = (n4 + 255) / 256;
    if (bblocks < 1) bblocks = 1;
    bucket_kernel<<<bblocks, 256>>>(
        (const float4*)dt, (const int4*)ids, (const int4*)segs,
        n4, dt, ids, segs, E, segs_per_win);

    // helper to zero window w
    auto zero_win = [&](int w) {
        long long seg_lo = (long long)w * segs_per_win;
        if (seg_lo >= n_out) return;
        long long seg_hi = seg_lo + segs_per_win;
        if (seg_hi > n_out) seg_hi = n_out;
        long long base_f = seg_lo * ROW;
        long long n4z    = ((seg_hi - seg_lo) * ROW) >> 2;
        long long zb     = (n4z + 255) / 256;
        zero_win_kernel<<<(unsigned)zb, 256>>>((float4*)(out + base_f), n4z);
    };

    int nwin_rt = (int)((n_out + segs_per_win - 1) / segs_per_win);

    // Software-pipelined: zero runs one window ahead of scatter, so the
    // eviction pressure (and thus the DRAM writeback drain) never starves.
    zero_win(0);
    if (nwin_rt > 1) zero_win(1);
    for (int w = 0; w < nwin_rt; w++) {
        scatter_bucket_kernel<<<SCAT_BLOCKS, 256>>>(decay, out, w);
        if (w + 2 < nwin_rt) zero_win(w + 2);
    }
}